// round 16
// baseline (speedup 1.0000x reference)
#include <cuda_runtime.h>
#include <cuda_bf16.h>
#include <cstdint>

#define BATCH   2
#define HIMG    256
#define WIMG    256
#define CH      96
#define C3      288
#define WINSZ   16
#define SEQ     256
#define NHEADS  4
#define HD      24
#define NWIN    512
#define NTOK    131072

typedef unsigned long long ull;

// ---------------- global scratch (bf16 interchange format) ------------------
__device__ __nv_bfloat16 g_qh [(size_t)NTOK * C3];   // qkv hi (q pre-scaled)
__device__ __nv_bfloat16 g_vlo[(size_t)NTOK * CH];   // v lo residual
__device__ __nv_bfloat16 g_ohi[(size_t)NTOK * CH];   // attention out hi
__device__ __nv_bfloat16 g_olo[(size_t)NTOK * CH];   // attention out lo
__device__ __nv_bfloat16 g_w1h[288 * 96], g_w1l[288 * 96];   // qkv_w  [n][k]
__device__ __nv_bfloat16 g_w2h[ 96 * 96], g_w2l[ 96 * 96];   // out_w  [n][k]

// ---------------- helpers ----------------------------------------------------
__device__ __forceinline__ uint32_t smem_u32(const void* p) {
    uint32_t a;
    asm("{ .reg .u64 t; cvta.to.shared.u64 t, %1; cvt.u32.u64 %0, t; }" : "=r"(a) : "l"(p));
    return a;
}
__device__ __forceinline__ void ldm_x4(uint32_t addr, uint32_t& r0, uint32_t& r1,
                                       uint32_t& r2, uint32_t& r3) {
    asm volatile("ldmatrix.sync.aligned.m8n8.x4.shared.b16 {%0,%1,%2,%3}, [%4];"
                 : "=r"(r0), "=r"(r1), "=r"(r2), "=r"(r3) : "r"(addr));
}
__device__ __forceinline__ void ldm_x4_trans(uint32_t addr, uint32_t& r0, uint32_t& r1,
                                             uint32_t& r2, uint32_t& r3) {
    asm volatile("ldmatrix.sync.aligned.m8n8.x4.trans.shared.b16 {%0,%1,%2,%3}, [%4];"
                 : "=r"(r0), "=r"(r1), "=r"(r2), "=r"(r3) : "r"(addr));
}
__device__ __forceinline__ void ldm_x2_trans(uint32_t addr, uint32_t& r0, uint32_t& r1) {
    asm volatile("ldmatrix.sync.aligned.m8n8.x2.trans.shared.b16 {%0,%1}, [%2];"
                 : "=r"(r0), "=r"(r1) : "r"(addr));
}
__device__ __forceinline__ void mma_bf16(float* c, const uint32_t* a, const uint32_t* b) {
    asm volatile(
        "mma.sync.aligned.m16n8k16.row.col.f32.bf16.bf16.f32 "
        "{%0,%1,%2,%3}, {%4,%5,%6,%7}, {%8,%9}, {%0,%1,%2,%3};"
        : "+f"(c[0]), "+f"(c[1]), "+f"(c[2]), "+f"(c[3])
        : "r"(a[0]), "r"(a[1]), "r"(a[2]), "r"(a[3]), "r"(b[0]), "r"(b[1]));
}
__device__ __forceinline__ void bf16split(float v, __nv_bfloat16& h, __nv_bfloat16& l) {
    h = __float2bfloat16(v);
    l = __float2bfloat16(v - __bfloat162float(h));
}
__device__ __forceinline__ uint32_t pack_bf2(__nv_bfloat16 a, __nv_bfloat16 b) {
    __nv_bfloat162 t(a, b);
    return *reinterpret_cast<uint32_t*>(&t);
}
__device__ __forceinline__ uint32_t cvt_bf16x2(float hi, float lo) {
    uint32_t r; asm("cvt.rn.bf16x2.f32 %0, %1, %2;" : "=r"(r) : "f"(hi), "f"(lo)); return r;
}
__device__ __forceinline__ float ex2f(float x) {
    float y; asm("ex2.approx.f32 %0, %1;" : "=f"(y) : "f"(x)); return y;
}

// ---------------------------------------------------------------------------
// One-time weight pre-conversion: W[k][n] fp32 -> [n][k] bf16 hi/lo planes.
// ---------------------------------------------------------------------------
__global__ __launch_bounds__(256)
void conv_w(const float* __restrict__ qkv_w, const float* __restrict__ out_w)
{
    int idx = blockIdx.x * 256 + threadIdx.x;
    if (idx < 288 * 96) {
        int n = idx / 96, k = idx - n * 96;
        __nv_bfloat16 h, l;
        bf16split(qkv_w[(size_t)k * 288 + n], h, l);
        g_w1h[idx] = h; g_w1l[idx] = l;
    } else {
        int j = idx - 288 * 96;
        if (j < 96 * 96) {
            int n = j / 96, k = j - n * 96;
            __nv_bfloat16 h, l;
            bf16split(out_w[(size_t)k * 96 + n], h, l);
            g_w2h[j] = h; g_w2l[j] = l;
        }
    }
}

// ---------------------------------------------------------------------------
// Tensor-core GEMM (mma.sync bf16, 3-term split) — unchanged from R15.
// ---------------------------------------------------------------------------
#define PITCH 104
#define S2F 0.29448899158937f   // (1/sqrt(24)) * log2(e)

__global__ __launch_bounds__(256, 2)
void gemm_mma(const float* __restrict__ A32,
              const __nv_bfloat16* __restrict__ Ahg, const __nv_bfloat16* __restrict__ Alg,
              const __nv_bfloat16* __restrict__ Whg, const __nv_bfloat16* __restrict__ Wlg,
              const float* __restrict__ bias, float* __restrict__ out32,
              __nv_bfloat16* __restrict__ oqh, __nv_bfloat16* __restrict__ ovlo,
              int ntiles)
{
    extern __shared__ __nv_bfloat16 smbf[];
    __nv_bfloat16* Ahi = smbf;
    __nv_bfloat16* Alo = Ahi + 128 * PITCH;
    __nv_bfloat16* Bhi = Alo + 128 * PITCH;
    __nv_bfloat16* Blo = Bhi + 96 * PITCH;

    const int tid  = threadIdx.x;
    const int lane = tid & 31;
    const int wid  = tid >> 5;
    const int m0   = blockIdx.x * 128;

    if (A32) {
        #pragma unroll
        for (int it = 0; it < 12; it++) {
            int idx = tid + it * 256;
            int m = idx / 24, q = idx - m * 24;
            float4 v = *(const float4*)(A32 + (size_t)(m0 + m) * CH + q * 4);
            __nv_bfloat16 h0, h1, h2, h3, l0, l1, l2, l3;
            bf16split(v.x, h0, l0); bf16split(v.y, h1, l1);
            bf16split(v.z, h2, l2); bf16split(v.w, h3, l3);
            *(uint2*)(Ahi + m * PITCH + q * 4) = make_uint2(pack_bf2(h0, h1), pack_bf2(h2, h3));
            *(uint2*)(Alo + m * PITCH + q * 4) = make_uint2(pack_bf2(l0, l1), pack_bf2(l2, l3));
        }
    } else {
        #pragma unroll
        for (int it = 0; it < 12; it++) {
            int idx = tid + it * 256;
            int plane = idx / 1536, j = idx - plane * 1536;
            int m = j / 12, q4 = j - m * 12;
            const __nv_bfloat16* src = (plane ? Alg : Ahg) + (size_t)(m0 + m) * 96 + q4 * 8;
            __nv_bfloat16* dst = (plane ? Alo : Ahi) + m * PITCH + q4 * 8;
            *(uint4*)dst = *(const uint4*)src;
        }
    }

    const int warp_m = wid & 3;
    const int warp_n = wid >> 2;

    const uint32_t a_row  = warp_m * 32 + (lane & 15);
    const uint32_t a_koff = (lane >> 4) * 8;
    const uint32_t aHi0 = smem_u32(Ahi + a_row * PITCH + a_koff);
    const uint32_t aLo0 = smem_u32(Alo + a_row * PITCH + a_koff);
    const uint32_t b_nrow = warp_n * 48 + (lane & 7) + ((lane >> 4) << 3);
    const uint32_t b_koff = ((lane >> 3) & 1) * 8;
    const uint32_t bHi0 = smem_u32(Bhi + b_nrow * PITCH + b_koff);
    const uint32_t bLo0 = smem_u32(Blo + b_nrow * PITCH + b_koff);

    for (int t = 0; t < ntiles; t++) {
        const int n0 = t * 96;
        if (t) __syncthreads();

        #pragma unroll
        for (int it = 0; it < 9; it++) {
            int idx = tid + it * 256;
            int plane = idx / 1152, j = idx - plane * 1152;
            int n = j / 12, q4 = j - n * 12;
            const __nv_bfloat16* src = (plane ? Wlg : Whg) + (size_t)(n0 + n) * 96 + q4 * 8;
            __nv_bfloat16* dst = (plane ? Blo : Bhi) + n * PITCH + q4 * 8;
            *(uint4*)dst = *(const uint4*)src;
        }
        __syncthreads();

        float acc[2][6][4];
        #pragma unroll
        for (int i = 0; i < 2; i++)
            #pragma unroll
            for (int j = 0; j < 6; j++)
                #pragma unroll
                for (int q = 0; q < 4; q++) acc[i][j][q] = 0.f;

        #pragma unroll
        for (int c = 0; c < 6; c++) {
            const uint32_t kb = c * 32;
            uint32_t ahi[2][4], alo[2][4];
            #pragma unroll
            for (int mt = 0; mt < 2; mt++) {
                ldm_x4(aHi0 + mt * (16 * PITCH * 2) + kb,
                       ahi[mt][0], ahi[mt][1], ahi[mt][2], ahi[mt][3]);
                ldm_x4(aLo0 + mt * (16 * PITCH * 2) + kb,
                       alo[mt][0], alo[mt][1], alo[mt][2], alo[mt][3]);
            }
            uint32_t bhi[6][2], blo[6][2];
            #pragma unroll
            for (int p = 0; p < 3; p++) {
                ldm_x4(bHi0 + p * (16 * PITCH * 2) + kb,
                       bhi[2 * p][0], bhi[2 * p][1], bhi[2 * p + 1][0], bhi[2 * p + 1][1]);
                ldm_x4(bLo0 + p * (16 * PITCH * 2) + kb,
                       blo[2 * p][0], blo[2 * p][1], blo[2 * p + 1][0], blo[2 * p + 1][1]);
            }
            #pragma unroll
            for (int nt = 0; nt < 6; nt++)
                #pragma unroll
                for (int mt = 0; mt < 2; mt++) {
                    mma_bf16(acc[mt][nt], ahi[mt], bhi[nt]);
                    mma_bf16(acc[mt][nt], ahi[mt], blo[nt]);
                    mma_bf16(acc[mt][nt], alo[mt], bhi[nt]);
                }
        }

        #pragma unroll
        for (int nt = 0; nt < 6; nt++) {
            int colbase = n0 + warp_n * 48 + nt * 8;
            int col = colbase + (lane & 3) * 2;
            float b0 = __ldg(bias + col), b1 = __ldg(bias + col + 1);
            int h = colbase / 72, r = colbase % 72;
            #pragma unroll
            for (int mt = 0; mt < 2; mt++) {
                int row0 = m0 + warp_m * 32 + mt * 16 + (lane >> 2);
                float v0 = acc[mt][nt][0] + b0, v1 = acc[mt][nt][1] + b1;
                float v2 = acc[mt][nt][2] + b0, v3 = acc[mt][nt][3] + b1;
                if (out32) {
                    *(float2*)(out32 + (size_t)row0 * CH + col)       = make_float2(v0, v1);
                    *(float2*)(out32 + (size_t)(row0 + 8) * CH + col) = make_float2(v2, v3);
                } else {
                    if (r < 24) { v0 *= S2F; v1 *= S2F; v2 *= S2F; v3 *= S2F; }
                    *(uint32_t*)(oqh + (size_t)row0 * C3 + col)       = cvt_bf16x2(v1, v0);
                    *(uint32_t*)(oqh + (size_t)(row0 + 8) * C3 + col) = cvt_bf16x2(v3, v2);
                    if (r >= 48) {
                        int vc = h * 24 + (r - 48) + (lane & 3) * 2;
                        __nv_bfloat16 h0, h1, h2, h3, l0, l1, l2, l3;
                        bf16split(v0, h0, l0); bf16split(v1, h1, l1);
                        bf16split(v2, h2, l2); bf16split(v3, h3, l3);
                        *(uint32_t*)(ovlo + (size_t)row0 * CH + vc)       = pack_bf2(l0, l1);
                        *(uint32_t*)(ovlo + (size_t)(row0 + 8) * CH + vc) = pack_bf2(l2, l3);
                    }
                }
            }
        }
    }
}

#define GEMM_MMA_SMEM ((2 * 128 * PITCH + 2 * 96 * PITCH) * (int)sizeof(__nv_bfloat16)) // 93184

// ---------------------------------------------------------------------------
// Tensor-core fused attention + lepe per (window, head).
// R16: QK back to k16-with-zeroed-pads (R14 numerics); key-block loop
// software-pipelined — K(kb+1) frags + S(kb+1) MMAs issued between the
// ex2/cvt chain and PV(kb), so tensor work overlaps the MUFU chain.
// ---------------------------------------------------------------------------
#define AP 40
#define ATT_SMEM (1024 * AP * 2)      // 81920 bytes: Qs,Ks,Vh,Vl planes

__global__ __launch_bounds__(256, 2)
void attn_mma(const __nv_bfloat16* __restrict__ qh, const __nv_bfloat16* __restrict__ vlo,
              const float* __restrict__ pe_w, const float* __restrict__ pe_b,
              __nv_bfloat16* __restrict__ ohi, __nv_bfloat16* __restrict__ olo)
{
    extern __shared__ __nv_bfloat16 asm_bf[];
    __nv_bfloat16* Qs = asm_bf;
    __nv_bfloat16* Ks = asm_bf + 256 * AP;
    __nv_bfloat16* Vh = asm_bf + 512 * AP;
    __nv_bfloat16* Vl = asm_bf + 768 * AP;

    const int tid  = threadIdx.x;
    const int lane = tid & 31;
    const int warp = tid >> 5;
    const int n    = blockIdx.x;
    const int h    = blockIdx.y;
    const int b    = n >> 8;
    const int rowbase = ((n >> 4) & 15) * 16;
    const int colbase = (n & 15) * 16;

    auto tok = [&](int s) -> int {
        int r = s >> 4, c = s & 15;
        return b * 65536 + (rowbase + r) * 256 + (colbase + c);
    };

    // ---- zero pad cols 24..31 of Q and K planes (rows 0..511) ----
    #pragma unroll
    for (int i = tid; i < 512; i += 256)
        *(uint4*)(asm_bf + i * AP + 24) = make_uint4(0, 0, 0, 0);

    // ---- load Q/K/Vh/Vl: pure uint4 copies (12 per token) ----
    #pragma unroll
    for (int it = 0; it < 12; it++) {
        int idx = tid + it * 256;            // 3072
        int s = idx / 12, sub = idx - s * 12;
        size_t base = (size_t)tok(s);
        uint4 v;
        if (sub < 9)
            v = *(const uint4*)(qh + base * C3 + h * 72 + sub * 8);
        else
            v = *(const uint4*)(vlo + base * CH + h * 24 + (sub - 9) * 8);
        int plane = (sub < 9) ? (sub / 3) : 3;
        int off   = (sub < 9) ? (sub % 3) * 8 : (sub - 9) * 8;
        *(uint4*)(asm_bf + plane * (256 * AP) + s * AP + off) = v;
    }
    __syncthreads();

    // ---- Q fragments: 2 k16 chunks (chunk1 cols 16-31, pads zeroed) ----
    uint32_t qa[2][2][4];
    #pragma unroll
    for (int mt = 0; mt < 2; mt++)
        #pragma unroll
        for (int kc = 0; kc < 2; kc++) {
            uint32_t addr = smem_u32(Qs + (warp * 32 + mt * 16 + (lane & 15)) * AP
                                        + kc * 16 + (lane >> 4) * 8);
            ldm_x4(addr, qa[mt][kc][0], qa[mt][kc][1], qa[mt][kc][2], qa[mt][kc][3]);
        }

    float O[2][3][4];
    #pragma unroll
    for (int mt = 0; mt < 2; mt++)
        #pragma unroll
        for (int dt = 0; dt < 3; dt++)
            #pragma unroll
            for (int q = 0; q < 4; q++) O[mt][dt][q] = 0.f;
    float lsum[2][2] = {{0.f, 0.f}, {0.f, 0.f}};

    const uint32_t k_row8 = (lane & 7) + ((lane >> 4) << 3);
    const uint32_t k_koff = ((lane >> 3) & 1) * 8;
    const uint32_t v_row8 = (lane & 7) + ((lane >> 3) & 1) * 8;
    const uint32_t v_dcol = ((lane >> 4) & 1) * 8;
    const uint32_t v_row2 = (lane & 15);

    // K fragment double buffer: [buf][nt][kc][2]
    uint32_t kf[2][2][2][2];
    float S[2][2][4];

    auto loadK = [&](int kb, int buf) {
        #pragma unroll
        for (int kc = 0; kc < 2; kc++) {
            uint32_t addr = smem_u32(Ks + (kb * 16 + k_row8) * AP + kc * 16 + k_koff);
            ldm_x4(addr, kf[buf][0][kc][0], kf[buf][0][kc][1],
                         kf[buf][1][kc][0], kf[buf][1][kc][1]);
        }
    };
    auto qkmma = [&](float (&Sx)[2][2][4], int buf) {
        #pragma unroll
        for (int mt = 0; mt < 2; mt++)
            #pragma unroll
            for (int nt = 0; nt < 2; nt++) {
                #pragma unroll
                for (int q = 0; q < 4; q++) Sx[mt][nt][q] = 0.f;
                mma_bf16(Sx[mt][nt], qa[mt][0], kf[buf][nt][0]);
                mma_bf16(Sx[mt][nt], qa[mt][1], kf[buf][nt][1]);
            }
    };

    // prologue: K(0) + S(0)
    loadK(0, 0);
    qkmma(S, 0);

    #pragma unroll
    for (int kb2 = 0; kb2 < 8; kb2++) {
        #pragma unroll
        for (int half = 0; half < 2; half++) {
            const int kb  = kb2 * 2 + half;   // unrolled: compile-time buf indices
            const int cur = half;
            const int nxt = half ^ 1;

            // V frags for kb (independent of softmax -> issue early)
            uint32_t vhf[3][2], vlf[3][2];
            {
                uint32_t ah = smem_u32(Vh + (kb * 16 + v_row8) * AP + v_dcol);
                uint32_t al = smem_u32(Vl + (kb * 16 + v_row8) * AP + v_dcol);
                ldm_x4_trans(ah, vhf[0][0], vhf[0][1], vhf[1][0], vhf[1][1]);
                ldm_x4_trans(al, vlf[0][0], vlf[0][1], vlf[1][0], vlf[1][1]);
                uint32_t ah2 = smem_u32(Vh + (kb * 16 + v_row2) * AP + 16);
                uint32_t al2 = smem_u32(Vl + (kb * 16 + v_row2) * AP + 16);
                ldm_x2_trans(ah2, vhf[2][0], vhf[2][1]);
                ldm_x2_trans(al2, vlf[2][0], vlf[2][1]);
            }

            // prefetch K(kb+1)
            if (kb < 15) loadK(kb + 1, nxt);

            // softmax on S(kb) -> ph (MUFU chain)
            uint32_t ph[2][4];
            #pragma unroll
            for (int mt = 0; mt < 2; mt++) {
                float p[2][4];
                #pragma unroll
                for (int nt = 0; nt < 2; nt++) {
                    #pragma unroll
                    for (int q = 0; q < 4; q++) p[nt][q] = ex2f(S[mt][nt][q]);
                    lsum[mt][0] += p[nt][0] + p[nt][1];
                    lsum[mt][1] += p[nt][2] + p[nt][3];
                }
                ph[mt][0] = cvt_bf16x2(p[0][1], p[0][0]);
                ph[mt][1] = cvt_bf16x2(p[0][3], p[0][2]);
                ph[mt][2] = cvt_bf16x2(p[1][1], p[1][0]);
                ph[mt][3] = cvt_bf16x2(p[1][3], p[1][2]);
            }

            // S(kb+1) MMAs — independent of ph; overlaps the MUFU chain
            if (kb < 15) qkmma(S, nxt);

            // PV MMAs for kb
            #pragma unroll
            for (int mt = 0; mt < 2; mt++)
                #pragma unroll
                for (int dt = 0; dt < 3; dt++) {
                    mma_bf16(O[mt][dt], ph[mt], vhf[dt]);
                    mma_bf16(O[mt][dt], ph[mt], vlf[dt]);
                }
            (void)cur;
        }
    }

    float inv[2][2];
    #pragma unroll
    for (int mt = 0; mt < 2; mt++)
        #pragma unroll
        for (int r = 0; r < 2; r++) {
            float v = lsum[mt][r];
            v += __shfl_xor_sync(0xffffffff, v, 1);
            v += __shfl_xor_sync(0xffffffff, v, 2);
            inv[mt][r] = 1.0f / v;
        }

    __syncthreads();
    float* osm = (float*)asm_bf;    // overlays dead Qs + head of Ks ([256][24] fp32)
    #pragma unroll
    for (int mt = 0; mt < 2; mt++) {
        int row = warp * 32 + mt * 16 + (lane >> 2);
        #pragma unroll
        for (int dt = 0; dt < 3; dt++) {
            int col = dt * 8 + (lane & 3) * 2;
            *(float2*)(osm + row * 24 + col) =
                make_float2(O[mt][dt][0] * inv[mt][0], O[mt][dt][1] * inv[mt][0]);
            *(float2*)(osm + (row + 8) * 24 + col) =
                make_float2(O[mt][dt][2] * inv[mt][1], O[mt][dt][3] * inv[mt][1]);
        }
    }
    __syncthreads();

    // ---- lepe + bias, then split to bf16 hi/lo and store ----
    {
        int s = tid;
        float o[24];
        #pragma unroll
        for (int i = 0; i < 6; i++) {
            float4 v4 = *(float4*)(osm + s * 24 + i * 4);
            o[4 * i] = v4.x; o[4 * i + 1] = v4.y; o[4 * i + 2] = v4.z; o[4 * i + 3] = v4.w;
        }
        int r = s >> 4, c = s & 15;
        #pragma unroll
        for (int ky = -1; ky <= 1; ky++) {
            int r2 = r + ky;
            if (r2 < 0 || r2 > 15) continue;
            #pragma unroll
            for (int kx = -1; kx <= 1; kx++) {
                int c2 = c + kx;
                if (c2 < 0 || c2 > 15) continue;
                const uint32_t* vh2 = (const uint32_t*)(Vh + (r2 * 16 + c2) * AP);
                const uint32_t* vl2 = (const uint32_t*)(Vl + (r2 * 16 + c2) * AP);
                const float* wrow = pe_w + ((ky + 1) * 3 + (kx + 1)) * CH + h * HD;
                #pragma unroll
                for (int i = 0; i < 12; i++) {
                    __nv_bfloat162 hb = *(const __nv_bfloat162*)&vh2[i];
                    __nv_bfloat162 lb = *(const __nv_bfloat162*)&vl2[i];
                    float2 hf = __bfloat1622float2(hb);
                    float2 lf = __bfloat1622float2(lb);
                    o[2 * i]     += (hf.x + lf.x) * __ldg(wrow + 2 * i);
                    o[2 * i + 1] += (hf.y + lf.y) * __ldg(wrow + 2 * i + 1);
                }
            }
        }
        #pragma unroll
        for (int d = 0; d < 24; d++) o[d] += __ldg(pe_b + h * HD + d);

        uint32_t hp[12], lp[12];
        #pragma unroll
        for (int i = 0; i < 12; i++) {
            __nv_bfloat16 h0, h1, l0, l1;
            bf16split(o[2 * i], h0, l0);
            bf16split(o[2 * i + 1], h1, l1);
            hp[i] = pack_bf2(h0, h1);
            lp[i] = pack_bf2(l0, l1);
        }
        size_t obase = (size_t)tok(s) * CH + h * HD;
        #pragma unroll
        for (int i = 0; i < 3; i++) {
            *(uint4*)(ohi + obase + i * 8) = make_uint4(hp[4*i], hp[4*i+1], hp[4*i+2], hp[4*i+3]);
            *(uint4*)(olo + obase + i * 8) = make_uint4(lp[4*i], lp[4*i+1], lp[4*i+2], lp[4*i+3]);
        }
    }
}

// ---------------------------------------------------------------------------
extern "C" void kernel_launch(void* const* d_in, const int* in_sizes, int n_in,
                              void* d_out, int out_size)
{
    const float* x     = (const float*)d_in[0];
    const float* qkv_w = (const float*)d_in[1];
    const float* qkv_b = (const float*)d_in[2];
    const float* pe_w  = (const float*)d_in[3];
    const float* pe_b  = (const float*)d_in[4];
    const float* out_w = (const float*)d_in[5];
    const float* out_b = (const float*)d_in[6];
    float* out = (float*)d_out;

    __nv_bfloat16 *qh, *vlo, *ohi, *olo, *w1h, *w1l, *w2h, *w2l;
    cudaGetSymbolAddress((void**)&qh,  g_qh);
    cudaGetSymbolAddress((void**)&vlo, g_vlo);
    cudaGetSymbolAddress((void**)&ohi, g_ohi);
    cudaGetSymbolAddress((void**)&olo, g_olo);
    cudaGetSymbolAddress((void**)&w1h, g_w1h);
    cudaGetSymbolAddress((void**)&w1l, g_w1l);
    cudaGetSymbolAddress((void**)&w2h, g_w2h);
    cudaGetSymbolAddress((void**)&w2l, g_w2l);

    cudaFuncSetAttribute(gemm_mma, cudaFuncAttributeMaxDynamicSharedMemorySize, GEMM_MMA_SMEM);
    cudaFuncSetAttribute(attn_mma, cudaFuncAttributeMaxDynamicSharedMemorySize, ATT_SMEM);

    // 0) one-time weight conversion
    conv_w<<<144, 256>>>(qkv_w, out_w);

    // 1) QKV projection -> bf16 planes (q pre-scaled, v split)
    gemm_mma<<<dim3(NTOK / 128, 1), 256, GEMM_MMA_SMEM>>>(
        x, nullptr, nullptr, w1h, w1l, qkv_b, nullptr, qh, vlo, 3);

    // 2) Fused windowed attention + lepe (pipelined) -> bf16 hi/lo o-planes
    attn_mma<<<dim3(NWIN, NHEADS), 256, ATT_SMEM>>>(qh, vlo, pe_w, pe_b, ohi, olo);

    // 3) Output projection (A = bf16 o-planes) -> fp32 out + bias
    gemm_mma<<<dim3(NTOK / 128, 1), 256, GEMM_MMA_SMEM>>>(
        nullptr, ohi, olo, w2h, w2l, out_b, out, nullptr, nullptr, 1);
}

// round 17
// speedup vs baseline: 1.0279x; 1.0279x over previous
#include <cuda_runtime.h>
#include <cuda_bf16.h>
#include <cstdint>

#define BATCH   2
#define HIMG    256
#define WIMG    256
#define CH      96
#define C3      288
#define WINSZ   16
#define SEQ     256
#define NHEADS  4
#define HD      24
#define NWIN    512
#define NTOK    131072

typedef unsigned long long ull;

// ---------------- global scratch (bf16 interchange format) ------------------
__device__ __nv_bfloat16 g_qh [(size_t)NTOK * C3];   // qkv hi (q pre-scaled)
__device__ __nv_bfloat16 g_vlo[(size_t)NTOK * CH];   // v lo residual
__device__ __nv_bfloat16 g_ohi[(size_t)NTOK * CH];   // attention out hi
__device__ __nv_bfloat16 g_olo[(size_t)NTOK * CH];   // attention out lo
__device__ __nv_bfloat16 g_w1h[288 * 96], g_w1l[288 * 96];   // qkv_w  [n][k]
__device__ __nv_bfloat16 g_w2h[ 96 * 96], g_w2l[ 96 * 96];   // out_w  [n][k]

// ---------------- helpers ----------------------------------------------------
__device__ __forceinline__ uint32_t smem_u32(const void* p) {
    uint32_t a;
    asm("{ .reg .u64 t; cvta.to.shared.u64 t, %1; cvt.u32.u64 %0, t; }" : "=r"(a) : "l"(p));
    return a;
}
__device__ __forceinline__ void ldm_x4(uint32_t addr, uint32_t& r0, uint32_t& r1,
                                       uint32_t& r2, uint32_t& r3) {
    asm volatile("ldmatrix.sync.aligned.m8n8.x4.shared.b16 {%0,%1,%2,%3}, [%4];"
                 : "=r"(r0), "=r"(r1), "=r"(r2), "=r"(r3) : "r"(addr));
}
__device__ __forceinline__ void ldm_x4_trans(uint32_t addr, uint32_t& r0, uint32_t& r1,
                                             uint32_t& r2, uint32_t& r3) {
    asm volatile("ldmatrix.sync.aligned.m8n8.x4.trans.shared.b16 {%0,%1,%2,%3}, [%4];"
                 : "=r"(r0), "=r"(r1), "=r"(r2), "=r"(r3) : "r"(addr));
}
__device__ __forceinline__ void ldm_x2_trans(uint32_t addr, uint32_t& r0, uint32_t& r1) {
    asm volatile("ldmatrix.sync.aligned.m8n8.x2.trans.shared.b16 {%0,%1}, [%2];"
                 : "=r"(r0), "=r"(r1) : "r"(addr));
}
__device__ __forceinline__ void mma_bf16(float* c, const uint32_t* a, const uint32_t* b) {
    asm volatile(
        "mma.sync.aligned.m16n8k16.row.col.f32.bf16.bf16.f32 "
        "{%0,%1,%2,%3}, {%4,%5,%6,%7}, {%8,%9}, {%0,%1,%2,%3};"
        : "+f"(c[0]), "+f"(c[1]), "+f"(c[2]), "+f"(c[3])
        : "r"(a[0]), "r"(a[1]), "r"(a[2]), "r"(a[3]), "r"(b[0]), "r"(b[1]));
}
__device__ __forceinline__ void bf16split(float v, __nv_bfloat16& h, __nv_bfloat16& l) {
    h = __float2bfloat16(v);
    l = __float2bfloat16(v - __bfloat162float(h));
}
__device__ __forceinline__ uint32_t pack_bf2(__nv_bfloat16 a, __nv_bfloat16 b) {
    __nv_bfloat162 t(a, b);
    return *reinterpret_cast<uint32_t*>(&t);
}
__device__ __forceinline__ uint32_t cvt_bf16x2(float hi, float lo) {
    uint32_t r; asm("cvt.rn.bf16x2.f32 %0, %1, %2;" : "=r"(r) : "f"(hi), "f"(lo)); return r;
}
__device__ __forceinline__ float ex2f(float x) {
    float y; asm("ex2.approx.f32 %0, %1;" : "=f"(y) : "f"(x)); return y;
}

// ---------------------------------------------------------------------------
// One-time weight pre-conversion: W[k][n] fp32 -> [n][k] bf16 hi/lo planes.
// ---------------------------------------------------------------------------
__global__ __launch_bounds__(256)
void conv_w(const float* __restrict__ qkv_w, const float* __restrict__ out_w)
{
    int idx = blockIdx.x * 256 + threadIdx.x;
    if (idx < 288 * 96) {
        int n = idx / 96, k = idx - n * 96;
        __nv_bfloat16 h, l;
        bf16split(qkv_w[(size_t)k * 288 + n], h, l);
        g_w1h[idx] = h; g_w1l[idx] = l;
    } else {
        int j = idx - 288 * 96;
        if (j < 96 * 96) {
            int n = j / 96, k = j - n * 96;
            __nv_bfloat16 h, l;
            bf16split(out_w[(size_t)k * 96 + n], h, l);
            g_w2h[j] = h; g_w2l[j] = l;
        }
    }
}

// ---------------------------------------------------------------------------
// Tensor-core GEMM (mma.sync bf16, 3-term split) — unchanged from R15/R16.
// ---------------------------------------------------------------------------
#define PITCH 104
#define S2F 0.29448899158937f   // (1/sqrt(24)) * log2(e)

__global__ __launch_bounds__(256, 2)
void gemm_mma(const float* __restrict__ A32,
              const __nv_bfloat16* __restrict__ Ahg, const __nv_bfloat16* __restrict__ Alg,
              const __nv_bfloat16* __restrict__ Whg, const __nv_bfloat16* __restrict__ Wlg,
              const float* __restrict__ bias, float* __restrict__ out32,
              __nv_bfloat16* __restrict__ oqh, __nv_bfloat16* __restrict__ ovlo,
              int ntiles)
{
    extern __shared__ __nv_bfloat16 smbf[];
    __nv_bfloat16* Ahi = smbf;
    __nv_bfloat16* Alo = Ahi + 128 * PITCH;
    __nv_bfloat16* Bhi = Alo + 128 * PITCH;
    __nv_bfloat16* Blo = Bhi + 96 * PITCH;

    const int tid  = threadIdx.x;
    const int lane = tid & 31;
    const int wid  = tid >> 5;
    const int m0   = blockIdx.x * 128;

    if (A32) {
        #pragma unroll
        for (int it = 0; it < 12; it++) {
            int idx = tid + it * 256;
            int m = idx / 24, q = idx - m * 24;
            float4 v = *(const float4*)(A32 + (size_t)(m0 + m) * CH + q * 4);
            __nv_bfloat16 h0, h1, h2, h3, l0, l1, l2, l3;
            bf16split(v.x, h0, l0); bf16split(v.y, h1, l1);
            bf16split(v.z, h2, l2); bf16split(v.w, h3, l3);
            *(uint2*)(Ahi + m * PITCH + q * 4) = make_uint2(pack_bf2(h0, h1), pack_bf2(h2, h3));
            *(uint2*)(Alo + m * PITCH + q * 4) = make_uint2(pack_bf2(l0, l1), pack_bf2(l2, l3));
        }
    } else {
        #pragma unroll
        for (int it = 0; it < 12; it++) {
            int idx = tid + it * 256;
            int plane = idx / 1536, j = idx - plane * 1536;
            int m = j / 12, q4 = j - m * 12;
            const __nv_bfloat16* src = (plane ? Alg : Ahg) + (size_t)(m0 + m) * 96 + q4 * 8;
            __nv_bfloat16* dst = (plane ? Alo : Ahi) + m * PITCH + q4 * 8;
            *(uint4*)dst = *(const uint4*)src;
        }
    }

    const int warp_m = wid & 3;
    const int warp_n = wid >> 2;

    const uint32_t a_row  = warp_m * 32 + (lane & 15);
    const uint32_t a_koff = (lane >> 4) * 8;
    const uint32_t aHi0 = smem_u32(Ahi + a_row * PITCH + a_koff);
    const uint32_t aLo0 = smem_u32(Alo + a_row * PITCH + a_koff);
    const uint32_t b_nrow = warp_n * 48 + (lane & 7) + ((lane >> 4) << 3);
    const uint32_t b_koff = ((lane >> 3) & 1) * 8;
    const uint32_t bHi0 = smem_u32(Bhi + b_nrow * PITCH + b_koff);
    const uint32_t bLo0 = smem_u32(Blo + b_nrow * PITCH + b_koff);

    for (int t = 0; t < ntiles; t++) {
        const int n0 = t * 96;
        if (t) __syncthreads();

        #pragma unroll
        for (int it = 0; it < 9; it++) {
            int idx = tid + it * 256;
            int plane = idx / 1152, j = idx - plane * 1152;
            int n = j / 12, q4 = j - n * 12;
            const __nv_bfloat16* src = (plane ? Wlg : Whg) + (size_t)(n0 + n) * 96 + q4 * 8;
            __nv_bfloat16* dst = (plane ? Blo : Bhi) + n * PITCH + q4 * 8;
            *(uint4*)dst = *(const uint4*)src;
        }
        __syncthreads();

        float acc[2][6][4];
        #pragma unroll
        for (int i = 0; i < 2; i++)
            #pragma unroll
            for (int j = 0; j < 6; j++)
                #pragma unroll
                for (int q = 0; q < 4; q++) acc[i][j][q] = 0.f;

        #pragma unroll
        for (int c = 0; c < 6; c++) {
            const uint32_t kb = c * 32;
            uint32_t ahi[2][4], alo[2][4];
            #pragma unroll
            for (int mt = 0; mt < 2; mt++) {
                ldm_x4(aHi0 + mt * (16 * PITCH * 2) + kb,
                       ahi[mt][0], ahi[mt][1], ahi[mt][2], ahi[mt][3]);
                ldm_x4(aLo0 + mt * (16 * PITCH * 2) + kb,
                       alo[mt][0], alo[mt][1], alo[mt][2], alo[mt][3]);
            }
            uint32_t bhi[6][2], blo[6][2];
            #pragma unroll
            for (int p = 0; p < 3; p++) {
                ldm_x4(bHi0 + p * (16 * PITCH * 2) + kb,
                       bhi[2 * p][0], bhi[2 * p][1], bhi[2 * p + 1][0], bhi[2 * p + 1][1]);
                ldm_x4(bLo0 + p * (16 * PITCH * 2) + kb,
                       blo[2 * p][0], blo[2 * p][1], blo[2 * p + 1][0], blo[2 * p + 1][1]);
            }
            #pragma unroll
            for (int nt = 0; nt < 6; nt++)
                #pragma unroll
                for (int mt = 0; mt < 2; mt++) {
                    mma_bf16(acc[mt][nt], ahi[mt], bhi[nt]);
                    mma_bf16(acc[mt][nt], ahi[mt], blo[nt]);
                    mma_bf16(acc[mt][nt], alo[mt], bhi[nt]);
                }
        }

        #pragma unroll
        for (int nt = 0; nt < 6; nt++) {
            int colbase = n0 + warp_n * 48 + nt * 8;
            int col = colbase + (lane & 3) * 2;
            float b0 = __ldg(bias + col), b1 = __ldg(bias + col + 1);
            int h = colbase / 72, r = colbase % 72;
            #pragma unroll
            for (int mt = 0; mt < 2; mt++) {
                int row0 = m0 + warp_m * 32 + mt * 16 + (lane >> 2);
                float v0 = acc[mt][nt][0] + b0, v1 = acc[mt][nt][1] + b1;
                float v2 = acc[mt][nt][2] + b0, v3 = acc[mt][nt][3] + b1;
                if (out32) {
                    *(float2*)(out32 + (size_t)row0 * CH + col)       = make_float2(v0, v1);
                    *(float2*)(out32 + (size_t)(row0 + 8) * CH + col) = make_float2(v2, v3);
                } else {
                    if (r < 24) { v0 *= S2F; v1 *= S2F; v2 *= S2F; v3 *= S2F; }
                    *(uint32_t*)(oqh + (size_t)row0 * C3 + col)       = cvt_bf16x2(v1, v0);
                    *(uint32_t*)(oqh + (size_t)(row0 + 8) * C3 + col) = cvt_bf16x2(v3, v2);
                    if (r >= 48) {
                        int vc = h * 24 + (r - 48) + (lane & 3) * 2;
                        __nv_bfloat16 h0, h1, h2, h3, l0, l1, l2, l3;
                        bf16split(v0, h0, l0); bf16split(v1, h1, l1);
                        bf16split(v2, h2, l2); bf16split(v3, h3, l3);
                        *(uint32_t*)(ovlo + (size_t)row0 * CH + vc)       = pack_bf2(l0, l1);
                        *(uint32_t*)(ovlo + (size_t)(row0 + 8) * CH + vc) = pack_bf2(l2, l3);
                    }
                }
            }
        }
    }
}

#define GEMM_MMA_SMEM ((2 * 128 * PITCH + 2 * 96 * PITCH) * (int)sizeof(__nv_bfloat16)) // 93184

// ---------------------------------------------------------------------------
// Tensor-core fused attention + lepe per (window, head).
// R17: loop body reverted EXACTLY to the R14 structure (fresh K frags per
// key-block, 2x k16 QK with zeroed pads, no double-buffer, no cross-iter
// state — R15/R16 additions pushed past the 128-reg cap and spilled).
// Keeps R15's bf16-plane I/O (pure-copy loads, pre-scaled Q, hi/lo o-out).
// ---------------------------------------------------------------------------
#define AP 40
#define ATT_SMEM (1024 * AP * 2)      // 81920 bytes: Qs,Ks,Vh,Vl planes

__global__ __launch_bounds__(256, 2)
void attn_mma(const __nv_bfloat16* __restrict__ qh, const __nv_bfloat16* __restrict__ vlo,
              const float* __restrict__ pe_w, const float* __restrict__ pe_b,
              __nv_bfloat16* __restrict__ ohi, __nv_bfloat16* __restrict__ olo)
{
    extern __shared__ __nv_bfloat16 asm_bf[];
    __nv_bfloat16* Qs = asm_bf;
    __nv_bfloat16* Ks = asm_bf + 256 * AP;
    __nv_bfloat16* Vh = asm_bf + 512 * AP;
    __nv_bfloat16* Vl = asm_bf + 768 * AP;

    const int tid  = threadIdx.x;
    const int lane = tid & 31;
    const int warp = tid >> 5;
    const int n    = blockIdx.x;
    const int h    = blockIdx.y;
    const int b    = n >> 8;
    const int rowbase = ((n >> 4) & 15) * 16;
    const int colbase = (n & 15) * 16;

    auto tok = [&](int s) -> int {
        int r = s >> 4, c = s & 15;
        return b * 65536 + (rowbase + r) * 256 + (colbase + c);
    };

    // ---- zero pad cols 24..31 of Q and K planes (rows 0..511) ----
    #pragma unroll
    for (int i = tid; i < 512; i += 256)
        *(uint4*)(asm_bf + i * AP + 24) = make_uint4(0, 0, 0, 0);

    // ---- load Q/K/Vh/Vl: pure uint4 copies (12 per token) ----
    #pragma unroll
    for (int it = 0; it < 12; it++) {
        int idx = tid + it * 256;            // 3072
        int s = idx / 12, sub = idx - s * 12;
        size_t base = (size_t)tok(s);
        uint4 v;
        if (sub < 9)
            v = *(const uint4*)(qh + base * C3 + h * 72 + sub * 8);
        else
            v = *(const uint4*)(vlo + base * CH + h * 24 + (sub - 9) * 8);
        int plane = (sub < 9) ? (sub / 3) : 3;
        int off   = (sub < 9) ? (sub % 3) * 8 : (sub - 9) * 8;
        *(uint4*)(asm_bf + plane * (256 * AP) + s * AP + off) = v;
    }
    __syncthreads();

    // ---- Q fragments: 2 k16 chunks (chunk1 cols 16-31, pads zeroed) ----
    uint32_t qa[2][2][4];
    #pragma unroll
    for (int mt = 0; mt < 2; mt++)
        #pragma unroll
        for (int kc = 0; kc < 2; kc++) {
            uint32_t addr = smem_u32(Qs + (warp * 32 + mt * 16 + (lane & 15)) * AP
                                        + kc * 16 + (lane >> 4) * 8);
            ldm_x4(addr, qa[mt][kc][0], qa[mt][kc][1], qa[mt][kc][2], qa[mt][kc][3]);
        }

    float O[2][3][4];
    #pragma unroll
    for (int mt = 0; mt < 2; mt++)
        #pragma unroll
        for (int dt = 0; dt < 3; dt++)
            #pragma unroll
            for (int q = 0; q < 4; q++) O[mt][dt][q] = 0.f;
    float lsum[2][2] = {{0.f, 0.f}, {0.f, 0.f}};

    const uint32_t k_row8 = (lane & 7) + ((lane >> 4) << 3);
    const uint32_t k_koff = ((lane >> 3) & 1) * 8;
    const uint32_t v_row8 = (lane & 7) + ((lane >> 3) & 1) * 8;
    const uint32_t v_dcol = ((lane >> 4) & 1) * 8;
    const uint32_t v_row2 = (lane & 15);

    for (int kb = 0; kb < 16; kb++) {
        // K fragments (fresh each block — R14 structure, no persistent state)
        uint32_t kf[2][2][2];
        #pragma unroll
        for (int kc = 0; kc < 2; kc++) {
            uint32_t addr = smem_u32(Ks + (kb * 16 + k_row8) * AP + kc * 16 + k_koff);
            ldm_x4(addr, kf[0][kc][0], kf[0][kc][1], kf[1][kc][0], kf[1][kc][1]);
        }

        float S[2][2][4];
        #pragma unroll
        for (int mt = 0; mt < 2; mt++)
            #pragma unroll
            for (int nt = 0; nt < 2; nt++) {
                #pragma unroll
                for (int q = 0; q < 4; q++) S[mt][nt][q] = 0.f;
                mma_bf16(S[mt][nt], qa[mt][0], kf[nt][0]);
                mma_bf16(S[mt][nt], qa[mt][1], kf[nt][1]);
            }

        uint32_t ph[2][4];
        #pragma unroll
        for (int mt = 0; mt < 2; mt++) {
            float p[2][4];
            #pragma unroll
            for (int nt = 0; nt < 2; nt++) {
                #pragma unroll
                for (int q = 0; q < 4; q++) p[nt][q] = ex2f(S[mt][nt][q]);
                lsum[mt][0] += p[nt][0] + p[nt][1];
                lsum[mt][1] += p[nt][2] + p[nt][3];
            }
            ph[mt][0] = cvt_bf16x2(p[0][1], p[0][0]);
            ph[mt][1] = cvt_bf16x2(p[0][3], p[0][2]);
            ph[mt][2] = cvt_bf16x2(p[1][1], p[1][0]);
            ph[mt][3] = cvt_bf16x2(p[1][3], p[1][2]);
        }

        uint32_t vhf[3][2], vlf[3][2];
        {
            uint32_t ah = smem_u32(Vh + (kb * 16 + v_row8) * AP + v_dcol);
            uint32_t al = smem_u32(Vl + (kb * 16 + v_row8) * AP + v_dcol);
            ldm_x4_trans(ah, vhf[0][0], vhf[0][1], vhf[1][0], vhf[1][1]);
            ldm_x4_trans(al, vlf[0][0], vlf[0][1], vlf[1][0], vlf[1][1]);
            uint32_t ah2 = smem_u32(Vh + (kb * 16 + v_row2) * AP + 16);
            uint32_t al2 = smem_u32(Vl + (kb * 16 + v_row2) * AP + 16);
            ldm_x2_trans(ah2, vhf[2][0], vhf[2][1]);
            ldm_x2_trans(al2, vlf[2][0], vlf[2][1]);
        }

        #pragma unroll
        for (int mt = 0; mt < 2; mt++)
            #pragma unroll
            for (int dt = 0; dt < 3; dt++) {
                mma_bf16(O[mt][dt], ph[mt], vhf[dt]);
                mma_bf16(O[mt][dt], ph[mt], vlf[dt]);
            }
    }

    float inv[2][2];
    #pragma unroll
    for (int mt = 0; mt < 2; mt++)
        #pragma unroll
        for (int r = 0; r < 2; r++) {
            float v = lsum[mt][r];
            v += __shfl_xor_sync(0xffffffff, v, 1);
            v += __shfl_xor_sync(0xffffffff, v, 2);
            inv[mt][r] = 1.0f / v;
        }

    __syncthreads();
    float* osm = (float*)asm_bf;    // overlays dead Qs + head of Ks ([256][24] fp32)
    #pragma unroll
    for (int mt = 0; mt < 2; mt++) {
        int row = warp * 32 + mt * 16 + (lane >> 2);
        #pragma unroll
        for (int dt = 0; dt < 3; dt++) {
            int col = dt * 8 + (lane & 3) * 2;
            *(float2*)(osm + row * 24 + col) =
                make_float2(O[mt][dt][0] * inv[mt][0], O[mt][dt][1] * inv[mt][0]);
            *(float2*)(osm + (row + 8) * 24 + col) =
                make_float2(O[mt][dt][2] * inv[mt][1], O[mt][dt][3] * inv[mt][1]);
        }
    }
    __syncthreads();

    // ---- lepe + bias, then split to bf16 hi/lo and store ----
    {
        int s = tid;
        float o[24];
        #pragma unroll
        for (int i = 0; i < 6; i++) {
            float4 v4 = *(float4*)(osm + s * 24 + i * 4);
            o[4 * i] = v4.x; o[4 * i + 1] = v4.y; o[4 * i + 2] = v4.z; o[4 * i + 3] = v4.w;
        }
        int r = s >> 4, c = s & 15;
        #pragma unroll
        for (int ky = -1; ky <= 1; ky++) {
            int r2 = r + ky;
            if (r2 < 0 || r2 > 15) continue;
            #pragma unroll
            for (int kx = -1; kx <= 1; kx++) {
                int c2 = c + kx;
                if (c2 < 0 || c2 > 15) continue;
                const uint32_t* vh2 = (const uint32_t*)(Vh + (r2 * 16 + c2) * AP);
                const uint32_t* vl2 = (const uint32_t*)(Vl + (r2 * 16 + c2) * AP);
                const float* wrow = pe_w + ((ky + 1) * 3 + (kx + 1)) * CH + h * HD;
                #pragma unroll
                for (int i = 0; i < 12; i++) {
                    __nv_bfloat162 hb = *(const __nv_bfloat162*)&vh2[i];
                    __nv_bfloat162 lb = *(const __nv_bfloat162*)&vl2[i];
                    float2 hf = __bfloat1622float2(hb);
                    float2 lf = __bfloat1622float2(lb);
                    o[2 * i]     += (hf.x + lf.x) * __ldg(wrow + 2 * i);
                    o[2 * i + 1] += (hf.y + lf.y) * __ldg(wrow + 2 * i + 1);
                }
            }
        }
        #pragma unroll
        for (int d = 0; d < 24; d++) o[d] += __ldg(pe_b + h * HD + d);

        uint32_t hp[12], lp[12];
        #pragma unroll
        for (int i = 0; i < 12; i++) {
            __nv_bfloat16 h0, h1, l0, l1;
            bf16split(o[2 * i], h0, l0);
            bf16split(o[2 * i + 1], h1, l1);
            hp[i] = pack_bf2(h0, h1);
            lp[i] = pack_bf2(l0, l1);
        }
        size_t obase = (size_t)tok(s) * CH + h * HD;
        #pragma unroll
        for (int i = 0; i < 3; i++) {
            *(uint4*)(ohi + obase + i * 8) = make_uint4(hp[4*i], hp[4*i+1], hp[4*i+2], hp[4*i+3]);
            *(uint4*)(olo + obase + i * 8) = make_uint4(lp[4*i], lp[4*i+1], lp[4*i+2], lp[4*i+3]);
        }
    }
}

// ---------------------------------------------------------------------------
extern "C" void kernel_launch(void* const* d_in, const int* in_sizes, int n_in,
                              void* d_out, int out_size)
{
    const float* x     = (const float*)d_in[0];
    const float* qkv_w = (const float*)d_in[1];
    const float* qkv_b = (const float*)d_in[2];
    const float* pe_w  = (const float*)d_in[3];
    const float* pe_b  = (const float*)d_in[4];
    const float* out_w = (const float*)d_in[5];
    const float* out_b = (const float*)d_in[6];
    float* out = (float*)d_out;

    __nv_bfloat16 *qh, *vlo, *ohi, *olo, *w1h, *w1l, *w2h, *w2l;
    cudaGetSymbolAddress((void**)&qh,  g_qh);
    cudaGetSymbolAddress((void**)&vlo, g_vlo);
    cudaGetSymbolAddress((void**)&ohi, g_ohi);
    cudaGetSymbolAddress((void**)&olo, g_olo);
    cudaGetSymbolAddress((void**)&w1h, g_w1h);
    cudaGetSymbolAddress((void**)&w1l, g_w1l);
    cudaGetSymbolAddress((void**)&w2h, g_w2h);
    cudaGetSymbolAddress((void**)&w2l, g_w2l);

    cudaFuncSetAttribute(gemm_mma, cudaFuncAttributeMaxDynamicSharedMemorySize, GEMM_MMA_SMEM);
    cudaFuncSetAttribute(attn_mma, cudaFuncAttributeMaxDynamicSharedMemorySize, ATT_SMEM);

    // 0) one-time weight conversion
    conv_w<<<144, 256>>>(qkv_w, out_w);

    // 1) QKV projection -> bf16 planes (q pre-scaled, v split)
    gemm_mma<<<dim3(NTOK / 128, 1), 256, GEMM_MMA_SMEM>>>(
        x, nullptr, nullptr, w1h, w1l, qkv_b, nullptr, qh, vlo, 3);

    // 2) Fused windowed attention + lepe -> bf16 hi/lo o-planes
    attn_mma<<<dim3(NWIN, NHEADS), 256, ATT_SMEM>>>(qh, vlo, pe_w, pe_b, ohi, olo);

    // 3) Output projection (A = bf16 o-planes) -> fp32 out + bias
    gemm_mma<<<dim3(NTOK / 128, 1), 256, GEMM_MMA_SMEM>>>(
        nullptr, ohi, olo, w2h, w2l, out_b, out, nullptr, nullptr, 1);
}